// round 1
// baseline (speedup 1.0000x reference)
#include <cuda_runtime.h>
#include <math.h>

#define T_TOTAL 32768
#define NEXP    64
#define HDIM    1024
#define TILE_T  128
#define KC      32
#define NTHREADS 256

// GEMM tile: 128 tokens x 64 experts, K-chunked by 32.
// Thread layout: tid = ty*8 + tx, ty in [0,32), tx in [0,8).
//   thread computes tokens ty*4 + {0..3}, experts tx*8 + {0..7}  (4x8 acc).
// Epilogue: the 8 lanes (tx=0..7) of a ty-group sit in one warp and jointly
// hold a token's 64 logits -> shuffle reductions, no shared round-trip.

__device__ __forceinline__ bool better(float v, int i, float ov, int oi) {
    // strictly greater value wins; on exact tie, lower expert index wins
    return (v > ov) || (v == ov && i < oi);
}

__global__ __launch_bounds__(NTHREADS)
void moe_gate_kernel(const float* __restrict__ x,
                     const float* __restrict__ W,
                     float* __restrict__ out,
                     int out_size)
{
    __shared__ float xs[TILE_T][KC + 1];  // +1 pad: conflict-free row reads
    __shared__ float ws[NEXP][KC + 1];

    const int tid = threadIdx.x;
    const int tx  = tid & 7;    // expert group
    const int ty  = tid >> 3;   // token group

    const int tok_base = blockIdx.x * TILE_T;
    const float* xblk = x + (size_t)tok_base * HDIM;

    float acc[4][8];
#pragma unroll
    for (int jt = 0; jt < 4; jt++)
#pragma unroll
        for (int je = 0; je < 8; je++) acc[jt][je] = 0.0f;

    for (int k0 = 0; k0 < HDIM; k0 += KC) {
        // load x tile: 128 tokens x 32 k -> 4096 floats, 16 per thread, coalesced
#pragma unroll
        for (int i = 0; i < 16; i++) {
            int idx = i * NTHREADS + tid;
            int tok = idx >> 5, k = idx & 31;
            xs[tok][k] = xblk[(size_t)tok * HDIM + k0 + k];
        }
        // load W tile: 64 experts x 32 k -> 2048 floats, 8 per thread
#pragma unroll
        for (int i = 0; i < 8; i++) {
            int idx = i * NTHREADS + tid;
            int e = idx >> 5, k = idx & 31;
            ws[e][k] = W[(size_t)e * HDIM + k0 + k];
        }
        __syncthreads();

#pragma unroll
        for (int kk = 0; kk < KC; kk++) {
            float a[4], b[8];
#pragma unroll
            for (int jt = 0; jt < 4; jt++) a[jt] = xs[ty * 4 + jt][kk];
#pragma unroll
            for (int je = 0; je < 8; je++) b[je] = ws[tx * 8 + je][kk];
#pragma unroll
            for (int jt = 0; jt < 4; jt++)
#pragma unroll
                for (int je = 0; je < 8; je++)
                    acc[jt][je] = fmaf(a[jt], b[je], acc[jt][je]);
        }
        __syncthreads();
    }

    // ------------- fused softmax + top-2 epilogue (8-lane shuffle groups) ----
    float* oscore = out;
    float* oidx   = out + 2 * (size_t)T_TOTAL;

#pragma unroll
    for (int jt = 0; jt < 4; jt++) {
        // local max over my 8 experts
        float m = acc[jt][0];
#pragma unroll
        for (int je = 1; je < 8; je++) m = fmaxf(m, acc[jt][je]);
        // group max (8 lanes)
#pragma unroll
        for (int off = 1; off < 8; off <<= 1)
            m = fmaxf(m, __shfl_xor_sync(0xffffffffu, m, off));

        // local sum of exp
        float s = 0.0f;
#pragma unroll
        for (int je = 0; je < 8; je++) s += expf(acc[jt][je] - m);
#pragma unroll
        for (int off = 1; off < 8; off <<= 1)
            s += __shfl_xor_sync(0xffffffffu, s, off);

        // local top-2 (ascending expert ids -> ties keep earlier idx)
        float v1 = acc[jt][0], v2 = -INFINITY;
        int   i1 = tx * 8,     i2 = NEXP;
#pragma unroll
        for (int je = 1; je < 8; je++) {
            float l = acc[jt][je];
            int   e = tx * 8 + je;
            if (l > v1)      { v2 = v1; i2 = i1; v1 = l; i1 = e; }
            else if (l > v2) { v2 = l;  i2 = e; }
        }
        // merge top-2 across the 8 lanes
#pragma unroll
        for (int off = 1; off < 8; off <<= 1) {
            float ov1 = __shfl_xor_sync(0xffffffffu, v1, off);
            int   oi1 = __shfl_xor_sync(0xffffffffu, i1, off);
            float ov2 = __shfl_xor_sync(0xffffffffu, v2, off);
            int   oi2 = __shfl_xor_sync(0xffffffffu, i2, off);
            if (better(ov1, oi1, v1, i1)) {
                if (better(v1, i1, ov2, oi2)) { v2 = v1; i2 = i1; }
                else                          { v2 = ov2; i2 = oi2; }
                v1 = ov1; i1 = oi1;
            } else {
                if (better(ov1, oi1, v2, i2)) { v2 = ov1; i2 = oi1; }
            }
        }

        if (tx == 0) {
            // p1 = exp(v1-m)/s, p2 = exp(v2-m)/s; out = softmax([p1, p2])
            float p1 = expf(v1 - m) / s;
            float p2 = expf(v2 - m) / s;
            float e21 = expf(p2 - p1);           // <= 1
            float s1  = 1.0f / (1.0f + e21);
            float s2  = e21 * s1;
            int t = tok_base + ty * 4 + jt;
            oscore[2 * t + 0] = s1;
            oscore[2 * t + 1] = s2;
            oidx[2 * t + 0]   = (float)i1;
            oidx[2 * t + 1]   = (float)i2;
        }
    }

    // tail (the scalar zero output, and anything past 4*T)
    if (blockIdx.x == 0 && tid < 32) {
        for (int p = 4 * T_TOTAL + tid; p < out_size; p += 32)
            out[p] = 0.0f;
    }
}

extern "C" void kernel_launch(void* const* d_in, const int* in_sizes, int n_in,
                              void* d_out, int out_size)
{
    const float* x = (const float*)d_in[0];
    const float* W = (const float*)d_in[1];
    float* out = (float*)d_out;
    moe_gate_kernel<<<T_TOTAL / TILE_T, NTHREADS>>>(x, W, out, out_size);
}

// round 2
// speedup vs baseline: 1.3048x; 1.3048x over previous
#include <cuda_runtime.h>
#include <math.h>

#define T_TOTAL 32768
#define NEXP    64
#define HDIM    1024
#define TILE_T  128
#define KC      32
#define NTHR    128
#define XPITCH  36          // floats; 16B-aligned rows, conflict-free quarter-warps

// Pre-transposed weights: Wt[k][e], k-major so the main kernel's W tile needs
// no in-kernel transpose (float4 all the way).
__device__ float g_Wt[HDIM * NEXP];

__global__ void transpose_w_kernel(const float* __restrict__ W) {
    int idx = blockIdx.x * blockDim.x + threadIdx.x;   // 65536 total
    int e = idx & (NEXP - 1);
    int k = idx >> 6;
    g_Wt[(size_t)k * NEXP + e] = W[(size_t)e * HDIM + k];
}

// packed f32x2 helpers
#define SPLAT2(d, f)   asm("mov.b64 %0, {%1, %1};" : "=l"(d) : "f"(f))
#define PACK2(d, a, b) asm("mov.b64 %0, {%1, %2};" : "=l"(d) : "f"(a), "f"(b))
#define UNPACK2(a, b, s) asm("mov.b64 {%0, %1}, %2;" : "=f"(a), "=f"(b) : "l"(s))
#define FMA2(acc, a, b) asm("fma.rn.f32x2 %0, %1, %2, %0;" : "+l"(acc) : "l"(a), "l"(b))

__device__ __forceinline__ bool better(float v, int i, float ov, int oi) {
    return (v > ov) || (v == ov && i < oi);
}

__global__ __launch_bounds__(NTHR, 4)
void moe_gate_kernel(const float* __restrict__ x,
                     float* __restrict__ out,
                     int out_size)
{
    __shared__ float xs[TILE_T][XPITCH];   // [tok][k] token-major
    __shared__ float ws[KC][NEXP];         // [k][e]  k-major

    const int tid = threadIdx.x;
    const int tx  = tid & 7;    // expert group: experts tx*8 .. tx*8+7
    const int ty  = tid >> 3;   // token group: tokens ty + 16*j, j=0..7

    const int tok_base = blockIdx.x * TILE_T;
    const float* xblk = x + (size_t)tok_base * HDIM;

    // accumulators: 8 tokens x 4 expert-pairs (f32x2)
    unsigned long long acc[8][4];
#pragma unroll
    for (int j = 0; j < 8; j++)
#pragma unroll
        for (int p = 0; p < 4; p++) acc[j][p] = 0ull;

    for (int k0 = 0; k0 < HDIM; k0 += KC) {
        // ---- load x tile: 128 tok x 32 k, float4, coalesced ----
#pragma unroll
        for (int i = 0; i < 8; i++) {
            int idx = i * NTHR + tid;
            int tok = idx >> 3, c = idx & 7;
            float4 v = *(const float4*)&xblk[(size_t)tok * HDIM + k0 + c * 4];
            *(float4*)&xs[tok][c * 4] = v;
        }
        // ---- load W tile: 32 k x 64 e, float4, coalesced (pre-transposed) ----
#pragma unroll
        for (int i = 0; i < 4; i++) {
            int idx = i * NTHR + tid;
            int r = idx >> 4, c4 = idx & 15;
            float4 v = *(const float4*)&g_Wt[(size_t)(k0 + r) * NEXP + c4 * 4];
            *(float4*)&ws[r][c4 * 4] = v;
        }
        __syncthreads();

#pragma unroll
        for (int kc4 = 0; kc4 < KC / 4; kc4++) {
            // b for 4 consecutive kk: 8 experts each -> 2 float4 per kk
            unsigned long long b2[4][4];
#pragma unroll
            for (int kk = 0; kk < 4; kk++) {
                float4 b0 = *(const float4*)&ws[kc4 * 4 + kk][tx * 8];
                float4 b1 = *(const float4*)&ws[kc4 * 4 + kk][tx * 8 + 4];
                PACK2(b2[kk][0], b0.x, b0.y);
                PACK2(b2[kk][1], b0.z, b0.w);
                PACK2(b2[kk][2], b1.x, b1.y);
                PACK2(b2[kk][3], b1.z, b1.w);
            }
#pragma unroll
            for (int j = 0; j < 8; j++) {
                float4 a = *(const float4*)&xs[ty + 16 * j][kc4 * 4];
                unsigned long long as;
                SPLAT2(as, a.x);
#pragma unroll
                for (int p = 0; p < 4; p++) FMA2(acc[j][p], as, b2[0][p]);
                SPLAT2(as, a.y);
#pragma unroll
                for (int p = 0; p < 4; p++) FMA2(acc[j][p], as, b2[1][p]);
                SPLAT2(as, a.z);
#pragma unroll
                for (int p = 0; p < 4; p++) FMA2(acc[j][p], as, b2[2][p]);
                SPLAT2(as, a.w);
#pragma unroll
                for (int p = 0; p < 4; p++) FMA2(acc[j][p], as, b2[3][p]);
            }
        }
        __syncthreads();
    }

    // ------------- fused softmax + top-2 epilogue (8-lane shuffle groups) ----
    float* oscore = out;
    float* oidx   = out + 2 * (size_t)T_TOTAL;

#pragma unroll
    for (int j = 0; j < 8; j++) {
        float l[8];
#pragma unroll
        for (int p = 0; p < 4; p++) UNPACK2(l[2 * p], l[2 * p + 1], acc[j][p]);

        // group max
        float m = l[0];
#pragma unroll
        for (int je = 1; je < 8; je++) m = fmaxf(m, l[je]);
#pragma unroll
        for (int off = 1; off < 8; off <<= 1)
            m = fmaxf(m, __shfl_xor_sync(0xffffffffu, m, off));

        // group sum of exp
        float s = 0.0f;
#pragma unroll
        for (int je = 0; je < 8; je++) s += expf(l[je] - m);
#pragma unroll
        for (int off = 1; off < 8; off <<= 1)
            s += __shfl_xor_sync(0xffffffffu, s, off);

        // local top-2 (ascending ids -> ties keep lower idx)
        float v1 = l[0], v2 = -INFINITY;
        int   i1 = tx * 8, i2 = NEXP;
#pragma unroll
        for (int je = 1; je < 8; je++) {
            float lv = l[je];
            int   e  = tx * 8 + je;
            if (lv > v1)      { v2 = v1; i2 = i1; v1 = lv; i1 = e; }
            else if (lv > v2) { v2 = lv; i2 = e; }
        }
        // merge across 8 lanes
#pragma unroll
        for (int off = 1; off < 8; off <<= 1) {
            float ov1 = __shfl_xor_sync(0xffffffffu, v1, off);
            int   oi1 = __shfl_xor_sync(0xffffffffu, i1, off);
            float ov2 = __shfl_xor_sync(0xffffffffu, v2, off);
            int   oi2 = __shfl_xor_sync(0xffffffffu, i2, off);
            if (better(ov1, oi1, v1, i1)) {
                if (better(v1, i1, ov2, oi2)) { v2 = v1; i2 = i1; }
                else                          { v2 = ov2; i2 = oi2; }
                v1 = ov1; i1 = oi1;
            } else {
                if (better(ov1, oi1, v2, i2)) { v2 = ov1; i2 = oi1; }
            }
        }

        if (tx == 0) {
            float p1 = expf(v1 - m) / s;
            float p2 = expf(v2 - m) / s;
            float e21 = expf(p2 - p1);
            float s1  = 1.0f / (1.0f + e21);
            float s2  = e21 * s1;
            int t = tok_base + ty + 16 * j;
            oscore[2 * t + 0] = s1;
            oscore[2 * t + 1] = s2;
            oidx[2 * t + 0]   = (float)i1;
            oidx[2 * t + 1]   = (float)i2;
        }
    }

    // tail (scalar zero output + anything past 4*T)
    if (blockIdx.x == 0 && tid < 32) {
        for (int p = 4 * T_TOTAL + tid; p < out_size; p += 32)
            out[p] = 0.0f;
    }
}

extern "C" void kernel_launch(void* const* d_in, const int* in_sizes, int n_in,
                              void* d_out, int out_size)
{
    const float* x = (const float*)d_in[0];
    const float* W = (const float*)d_in[1];
    float* out = (float*)d_out;

    transpose_w_kernel<<<256, 256>>>(W);
    moe_gate_kernel<<<T_TOTAL / TILE_T, NTHR>>>(x, out, out_size);
}